// round 14
// baseline (speedup 1.0000x reference)
#include <cuda_runtime.h>
#include <math.h>

// Problem constants
#define BATCH 4
#define NSEQ  4096
#define DIM   512
#define KH    64
#define MTOT  (BATCH*NSEQ)      // 16384
#define NCH   512               // prefix chunks per batch
#define CHLEN (NSEQ/NCH)        // 8
#define SN    2048              // sub-sort size

typedef unsigned long long ull;

#define FMA2(d, a, b) \
    asm("fma.rn.f32x2 %0, %1, %2, %0;" : "+l"(d) : "l"(a), "l"(b))
#define PACK2(out, f) \
    asm("mov.b64 %0, {%1, %1};" : "=l"(out) : "r"(__float_as_uint(f)))
#define UNPACK2(lo, hi, v) \
    do { unsigned int _l, _h; \
         asm("mov.b64 {%0, %1}, %2;" : "=r"(_l), "=r"(_h) : "l"(v)); \
         lo = __uint_as_float(_l); hi = __uint_as_float(_h); } while (0)

// ---------------- scratch ------------------------------------------------------------
__device__ __align__(16) float g_h[MTOT*KH];          // 4 MB projected feats
__device__ __align__(16) float g_wb[DIM];
__device__ __align__(16) float g_wc[DIM];
__device__ float g_t1[MTOT];
__device__ float g_t2[MTOT];
__device__ __align__(16) ull g_skey[BATCH][NSEQ];     // per-half sorted keys
__device__ float g_t2s[BATCH][NSEQ];                  // t2 sorted descending
__device__ int   g_perm[BATCH][NSEQ];
// chunk totals [b][k][c] (coalesced for scan loads)
__device__ __align__(16) float g_tot1[BATCH][KH][NCH];
__device__ __align__(16) float g_tot2[BATCH][KH][NCH];
__device__ __align__(16) float g_totz1[BATCH][NCH];
__device__ __align__(16) float g_totz2[BATCH][NCH];
// transposed exclusive offsets [b][c][k] (+ totals at c=NCH), coalesced for k_out
__device__ __align__(16) float g_off1T[BATCH][NCH+1][KH];
__device__ __align__(16) float g_off2T[BATCH][NCH+1][KH];
__device__ float g_offz1[BATCH][NCH+1];
__device__ float g_offz2[BATCH][NCH+1];

// ---------------- K0a: fold weights ---------------------------------------------------
__global__ void k_fold(const float* __restrict__ Wa, const float* __restrict__ Wb,
                       const float* __restrict__ Wc) {
    int d = threadIdx.x;                  // 512 threads
    float sb = 0.f, sc = 0.f;
#pragma unroll 8
    for (int k = 0; k < KH; k++) {
        float w = Wa[(size_t)k*DIM + d];
        sb += w * Wb[k];
        sc += w * Wc[k];
    }
    g_wb[d] = sb;
    g_wc[d] = sc;
}

// ---------------- K0b: t1/t2 directly from x (one warp per row) ----------------------
__global__ void k_t12(const float* __restrict__ x,
                      const float* __restrict__ wb_bias,
                      const float* __restrict__ wc_bias) {
    int lane = threadIdx.x & 31;
    int warp = threadIdx.x >> 5;          // 4 warps/block
    int row  = blockIdx.x*4 + warp;
    const float4* xr  = reinterpret_cast<const float4*>(x + (size_t)row*DIM);
    const float4* wb4 = reinterpret_cast<const float4*>(g_wb);
    const float4* wc4 = reinterpret_cast<const float4*>(g_wc);
    float s1 = 0.f, s2 = 0.f;
#pragma unroll
    for (int i = 0; i < 4; i++) {
        float4 xv = xr[lane + 32*i];
        float4 bv = wb4[lane + 32*i];
        float4 cv = wc4[lane + 32*i];
        s1 += xv.x*bv.x + xv.y*bv.y + xv.z*bv.z + xv.w*bv.w;
        s2 += xv.x*cv.x + xv.y*cv.y + xv.z*cv.z + xv.w*cv.w;
    }
#pragma unroll
    for (int s = 16; s; s >>= 1) {
        s1 += __shfl_xor_sync(0xFFFFFFFFu, s1, s);
        s2 += __shfl_xor_sync(0xFFFFFFFFu, s2, s);
    }
    if (lane == 0) {
        g_t1[row] = s1 + wb_bias[0];
        g_t2[row] = s2 + wc_bias[0];
    }
}

// ---------------- K1: h = x @ Wa^T, f32x2, 8x8 thread tile, reg prefetch -------------
__global__ void __launch_bounds__(128, 1)
k_gemm(const float* __restrict__ x, const float* __restrict__ Wa) {
    __shared__ __align__(16) float Xs[16*132];   // [dd][m], padded
    __shared__ __align__(16) float Ws[16*64];    // [dd][k]
    const int t  = threadIdx.x;          // 0..127
    const int m0 = blockIdx.x * 128;
    const int tm = t >> 3;               // 0..15 -> rows tm*8..+7 (4 pairs)
    const int tk = t & 7;                // 0..7  -> cols tk*8..+7

    // loader indices: Xs needs 512 float4 (4/thread), Ws 256 float4 (2/thread)
    int xm[4], xdg[4], wk[2], wdg[2];
    const float *xp[4], *wp[2];
#pragma unroll
    for (int l = 0; l < 4; l++) {
        int q = t + l*128;
        xdg[l] = q & 3;  xm[l] = q >> 2;
        xp[l] = x + (size_t)(m0 + xm[l])*DIM + xdg[l]*4;
    }
#pragma unroll
    for (int l = 0; l < 2; l++) {
        int q = t + l*128;
        wdg[l] = q & 3;  wk[l] = q >> 2;
        wp[l] = Wa + (size_t)wk[l]*DIM + wdg[l]*4;
    }

    ull acc2[4][8];                      // [row-pair][col]
#pragma unroll
    for (int j = 0; j < 4; j++)
#pragma unroll
        for (int c = 0; c < 8; c++) acc2[j][c] = 0ull;

    float4 rx[4], rw[2];
#pragma unroll
    for (int l = 0; l < 4; l++) rx[l] = *reinterpret_cast<const float4*>(xp[l]);
#pragma unroll
    for (int l = 0; l < 2; l++) rw[l] = *reinterpret_cast<const float4*>(wp[l]);

    for (int d0 = 0; d0 < DIM; d0 += 16) {
#pragma unroll
        for (int l = 0; l < 4; l++) {
            Xs[(xdg[l]*4+0)*132 + xm[l]] = rx[l].x;
            Xs[(xdg[l]*4+1)*132 + xm[l]] = rx[l].y;
            Xs[(xdg[l]*4+2)*132 + xm[l]] = rx[l].z;
            Xs[(xdg[l]*4+3)*132 + xm[l]] = rx[l].w;
        }
#pragma unroll
        for (int l = 0; l < 2; l++) {
            Ws[(wdg[l]*4+0)*64 + wk[l]] = rw[l].x;
            Ws[(wdg[l]*4+1)*64 + wk[l]] = rw[l].y;
            Ws[(wdg[l]*4+2)*64 + wk[l]] = rw[l].z;
            Ws[(wdg[l]*4+3)*64 + wk[l]] = rw[l].w;
        }
        __syncthreads();

        if (d0 + 16 < DIM) {
#pragma unroll
            for (int l = 0; l < 4; l++)
                rx[l] = *reinterpret_cast<const float4*>(xp[l] + d0 + 16);
#pragma unroll
            for (int l = 0; l < 2; l++)
                rw[l] = *reinterpret_cast<const float4*>(wp[l] + d0 + 16);
        }

#pragma unroll
        for (int dd = 0; dd < 16; dd++) {
            ulonglong2 xa = *reinterpret_cast<const ulonglong2*>(Xs + dd*132 + tm*8);
            ulonglong2 xb = *reinterpret_cast<const ulonglong2*>(Xs + dd*132 + tm*8 + 4);
            float4 wv0 = *reinterpret_cast<const float4*>(Ws + dd*64 + tk*8);
            float4 wv1 = *reinterpret_cast<const float4*>(Ws + dd*64 + tk*8 + 4);
            ull wd[8];
            PACK2(wd[0], wv0.x); PACK2(wd[1], wv0.y);
            PACK2(wd[2], wv0.z); PACK2(wd[3], wv0.w);
            PACK2(wd[4], wv1.x); PACK2(wd[5], wv1.y);
            PACK2(wd[6], wv1.z); PACK2(wd[7], wv1.w);
            ull xpq[4] = {xa.x, xa.y, xb.x, xb.y};
#pragma unroll
            for (int j = 0; j < 4; j++)
#pragma unroll
                for (int c = 0; c < 8; c++)
                    FMA2(acc2[j][c], xpq[j], wd[c]);
        }
        __syncthreads();
    }

#pragma unroll
    for (int j = 0; j < 4; j++) {
        float lo[8], hi[8];
#pragma unroll
        for (int c = 0; c < 8; c++) UNPACK2(lo[c], hi[c], acc2[j][c]);
        int mlo = m0 + tm*8 + 2*j;
        *reinterpret_cast<float4*>(g_h + (size_t)mlo*KH + tk*8) =
            make_float4(lo[0], lo[1], lo[2], lo[3]);
        *reinterpret_cast<float4*>(g_h + (size_t)mlo*KH + tk*8 + 4) =
            make_float4(lo[4], lo[5], lo[6], lo[7]);
        *reinterpret_cast<float4*>(g_h + (size_t)(mlo+1)*KH + tk*8) =
            make_float4(hi[0], hi[1], hi[2], hi[3]);
        *reinterpret_cast<float4*>(g_h + (size_t)(mlo+1)*KH + tk*8 + 4) =
            make_float4(hi[4], hi[5], hi[6], hi[7]);
    }
}

// ---------------- K2a: bitonic sort of 2048-element halves ----------------------------
__device__ __forceinline__ unsigned int fmap(float f) {
    unsigned int u = __float_as_uint(f);
    return (u & 0x80000000u) ? ~u : (u | 0x80000000u);
}
__device__ __forceinline__ float funmap(unsigned int u) {
    u = (u & 0x80000000u) ? (u & 0x7FFFFFFFu) : ~u;
    return __uint_as_float(u);
}

__global__ void k_sort2048() {
    __shared__ ull sv[SN];                   // 16 KB
    int b = blockIdx.x >> 1, half = blockIdx.x & 1;
    int tid = threadIdx.x;                   // 1024 threads
    for (int r = tid; r < SN; r += 1024) {
        int gi = half*SN + r;
        unsigned int u = fmap(g_t2[b*NSEQ + gi]);
        sv[r] = ((ull)u << 32) | (unsigned int)gi;
    }
    __syncthreads();
    int lane = tid & 31, warp = tid >> 5;
    for (int k = 2; k <= SN; k <<= 1) {
        for (int s = k >> 1; s >= 32; s >>= 1) {
#pragma unroll 1
            for (int t = tid; t < SN/2; t += 1024) {
                int i = ((t & ~(s-1)) << 1) | (t & (s-1));
                int j = i + s;
                bool desc = ((i & k) == 0);
                ull a = sv[i], c = sv[j];
                bool sw = desc ? (a < c) : (a > c);
                if (sw) { sv[i] = c; sv[j] = a; }
            }
            __syncthreads();
        }
        {
            int smax = ((k >> 1) < 32) ? (k >> 1) : 16;
#pragma unroll 1
            for (int g = warp; g < SN/32; g += 32) {
                int i = g*32 + lane;
                ull val = sv[i];
                bool desc = ((i & k) == 0);
#pragma unroll 1
                for (int s = smax; s >= 1; s >>= 1) {
                    ull other = __shfl_xor_sync(0xFFFFFFFFu, val, s);
                    bool upper = (lane & s) != 0;
                    bool takeMax = (upper != desc);
                    bool otherBigger = (other > val);
                    val = (takeMax == otherBigger) ? other : val;
                }
                sv[i] = val;
            }
            __syncthreads();
        }
    }
    for (int r = tid; r < SN; r += 1024)
        g_skey[b][half*SN + r] = sv[r];
}

// ---------------- K2b: merge (8 blocks; each ranks one half) --------------------------
__global__ void k_merge() {
    __shared__ ull sk[2*SN];                 // 32 KB
    int b = blockIdx.x >> 1, half = blockIdx.x & 1;
    int tid = threadIdx.x;                   // 1024 threads
    for (int r = tid; r < 2*SN; r += 1024)
        sk[r] = g_skey[b][r];
    __syncthreads();
#pragma unroll
    for (int q = 0; q < 2; q++) {
        int e = half*SN + tid + q*1024;
        ull key = sk[e];
        int ownIdx = e - half*SN;
        const ull* other = half ? sk : (sk + SN);
        int lo = 0, hi = SN;                 // count of other[] strictly greater
        while (lo < hi) {
            int mid = (lo + hi) >> 1;
            if (other[mid] > key) lo = mid + 1; else hi = mid;
        }
        int rank = ownIdx + lo;
        g_t2s[b][rank]  = funmap((unsigned int)(key >> 32));
        g_perm[b][rank] = (int)(key & 0xFFFFFFFFu);
    }
}

// ---------------- K3a: per-chunk totals ------------------------------------------------
__global__ void k_psum_a() {
    int b = blockIdx.x >> 9;              // NCH=512
    int c = blockIdx.x & 511;
    int k = threadIdx.x;                  // 64 threads
    int r0 = c * CHLEN;
    float m2 = g_t2s[b][0];
    float s1=0.f, s2=0.f, z1=0.f, z2=0.f;
#pragma unroll
    for (int r = r0; r < r0 + CHLEN; r++) {
        float tv = g_t2s[b][r] - m2;
        float e1 = expf(tv);
        float e2 = expf(0.2f*tv);
        int   j  = g_perm[b][r];
        float hv = g_h[((size_t)b*NSEQ + j)*KH + k];
        s1 += e1*hv;  s2 += e2*hv;
        z1 += e1;     z2 += e2;
    }
    g_tot1[b][k][c] = s1;  g_tot2[b][k][c] = s2;
    if (k == 0) { g_totz1[b][c] = z1; g_totz2[b][c] = z2; }
}

// ---------------- K3b: scan -> transposed offsets + totals ----------------------------
__global__ void k_scan() {
    int b = blockIdx.x >> 6, k = blockIdx.x & 63;
    int warp = threadIdx.x >> 5, lane = threadIdx.x & 31;
    if (warp == 0) {
        const float4* p1 = reinterpret_cast<const float4*>(&g_tot1[b][k][lane*16]);
        const float4* p2 = reinterpret_cast<const float4*>(&g_tot2[b][k][lane*16]);
        float v1[16], v2[16];
#pragma unroll
        for (int g = 0; g < 4; g++) {
            float4 a = p1[g], d = p2[g];
            v1[g*4+0]=a.x; v1[g*4+1]=a.y; v1[g*4+2]=a.z; v1[g*4+3]=a.w;
            v2[g*4+0]=d.x; v2[g*4+1]=d.y; v2[g*4+2]=d.z; v2[g*4+3]=d.w;
        }
        float t1 = 0.f, t2 = 0.f;
#pragma unroll
        for (int i = 0; i < 16; i++) {
            float a = v1[i], d = v2[i];
            v1[i] = t1; t1 += a;
            v2[i] = t2; t2 += d;
        }
        float e1 = t1, e2 = t2;
#pragma unroll
        for (int s = 1; s < 32; s <<= 1) {
            float o1 = __shfl_up_sync(0xFFFFFFFFu, e1, s);
            float o2 = __shfl_up_sync(0xFFFFFFFFu, e2, s);
            if (lane >= s) { e1 += o1; e2 += o2; }
        }
        e1 -= t1; e2 -= t2;                  // exclusive lane base
#pragma unroll
        for (int i = 0; i < 16; i++) {
            int c = lane*16 + i;
            g_off1T[b][c][k] = e1 + v1[i];
            g_off2T[b][c][k] = e2 + v2[i];
        }
        if (lane == 31) {                    // inclusive totals at c = NCH
            g_off1T[b][NCH][k] = e1 + t1;
            g_off2T[b][NCH][k] = e2 + t2;
        }
    } else if (k == 0) {
        float v1[16], v2[16];
        float t1 = 0.f, t2 = 0.f;
#pragma unroll
        for (int i = 0; i < 16; i++) {
            int c = lane*16 + i;
            float a = g_totz1[b][c];
            float d = g_totz2[b][c];
            v1[i] = t1; t1 += a;
            v2[i] = t2; t2 += d;
        }
        float e1 = t1, e2 = t2;
#pragma unroll
        for (int s = 1; s < 32; s <<= 1) {
            float o1 = __shfl_up_sync(0xFFFFFFFFu, e1, s);
            float o2 = __shfl_up_sync(0xFFFFFFFFu, e2, s);
            if (lane >= s) { e1 += o1; e2 += o2; }
        }
        e1 -= t1; e2 -= t2;
#pragma unroll
        for (int i = 0; i < 16; i++) {
            int c = lane*16 + i;
            g_offz1[b][c] = e1 + v1[i];
            g_offz2[b][c] = e2 + v2[i];
        }
        if (lane == 31) {
            g_offz1[b][NCH] = e1 + t1;
            g_offz2[b][NCH] = e2 + t2;
        }
    }
}

// ---------------- K4: output: search + on-the-fly chunk-local prefix ------------------
__global__ void k_out(float* __restrict__ out, const float* __restrict__ bias) {
    int lane = threadIdx.x & 31;
    int warp = threadIdx.x >> 5;          // 8 warps -> 8 rows per block
    int row  = blockIdx.x*8 + warp;
    int b    = row >> 12;

    float t1v = g_t1[row];
    float m2  = g_t2s[b][0];
    float u   = t1v + m2;
    float M   = (u > 0.f) ? u : 0.2f*u;
    float c1  = expf(u - M);
    float c2  = expf(0.2f*u - M);
    float tau = -t1v;

    const float* t2s = g_t2s[b];
    unsigned int b0 = __ballot_sync(0xFFFFFFFFu, t2s[lane*128]      > tau);
    unsigned int b1 = __ballot_sync(0xFFFFFFFFu, t2s[lane*128 + 64] > tau);
    int count1 = __popc(b0) + __popc(b1);
    int base   = count1 ? (count1 - 1) * 64 : 0;
    unsigned int d0 = __ballot_sync(0xFFFFFFFFu, t2s[base + lane]      > tau);
    unsigned int d1 = __ballot_sync(0xFFFFFFFFu, t2s[base + 32 + lane] > tau);
    int p = base + __popc(d0) + __popc(d1);

    int cp = p >> 3;                       // chunk index (cp=NCH iff p=NSEQ)
    int r0 = cp * CHLEN;
    int cnt = p - r0;

    int k0 = lane, k1 = lane + 32;
    float a1_0 = g_off1T[b][cp][k0], a1_1 = g_off1T[b][cp][k1];
    float a2_0 = g_off2T[b][cp][k0], a2_1 = g_off2T[b][cp][k1];
    float z1 = g_offz1[b][cp], z2 = g_offz2[b][cp];

#pragma unroll 1
    for (int r = r0; r < r0 + cnt; r++) {
        float tv = t2s[r] - m2;
        float e1 = expf(tv);
        float e2 = expf(0.2f*tv);
        int   j  = g_perm[b][r];
        const float* hr = g_h + ((size_t)b*NSEQ + j)*KH;
        float h0 = hr[k0], h1 = hr[k1];
        a1_0 += e1*h0;  a1_1 += e1*h1;
        a2_0 += e2*h0;  a2_1 += e2*h1;
        z1 += e1;  z2 += e2;
    }

    float Btot0 = g_off2T[b][NCH][k0];
    float Btot1 = g_off2T[b][NCH][k1];
    float Z2tot = g_offz2[b][NCH];
    float inv_den = 1.0f / (c1*z1 + c2*(Z2tot - z2));

    out[(size_t)row*KH + k0] = (c1*a1_0 + c2*(Btot0 - a2_0))*inv_den + bias[k0];
    out[(size_t)row*KH + k1] = (c1*a1_1 + c2*(Btot1 - a2_1))*inv_den + bias[k1];
}

// ---------------- stream/event objects ------------------------------------------------
struct ForkCtx {
    cudaStream_t s2;
    cudaEvent_t  evA, evB;
    ForkCtx() {
        cudaStreamCreateWithFlags(&s2, cudaStreamNonBlocking);
        cudaEventCreateWithFlags(&evA, cudaEventDisableTiming);
        cudaEventCreateWithFlags(&evB, cudaEventDisableTiming);
    }
};
static ForkCtx g_fork;

// ---------------- launch ---------------------------------------------------------------
extern "C" void kernel_launch(void* const* d_in, const int* in_sizes, int n_in,
                              void* d_out, int out_size) {
    const float* x       = (const float*)d_in[0];
    const float* Wa      = (const float*)d_in[1];
    const float* Wb      = (const float*)d_in[2];
    const float* wb_bias = (const float*)d_in[3];
    const float* Wc      = (const float*)d_in[4];
    const float* wc_bias = (const float*)d_in[5];
    const float* bias    = (const float*)d_in[6];
    float* out = (float*)d_out;

    k_fold<<<1, 512>>>(Wa, Wb, Wc);
    k_t12 <<<MTOT/4, 128>>>(x, wb_bias, wc_bias);
    cudaEventRecord(g_fork.evA, 0);
    cudaStreamWaitEvent(g_fork.s2, g_fork.evA, 0);
    k_sort2048<<<BATCH*2, 1024, 0, g_fork.s2>>>();
    k_merge   <<<BATCH*2, 1024, 0, g_fork.s2>>>();
    cudaEventRecord(g_fork.evB, g_fork.s2);

    k_gemm<<<MTOT/128, 128>>>(x, Wa);        // concurrent with sort path

    cudaStreamWaitEvent(0, g_fork.evB, 0);   // join
    k_psum_a<<<BATCH*NCH,  64>>>();
    k_scan  <<<BATCH*KH,   64>>>();
    k_out   <<<MTOT/8,   256>>>(out, bias);
}

// round 15
// speedup vs baseline: 1.0770x; 1.0770x over previous
#include <cuda_runtime.h>
#include <math.h>

// Problem constants
#define BATCH 4
#define NSEQ  4096
#define DIM   512
#define KH    64
#define MTOT  (BATCH*NSEQ)      // 16384
#define NCH   512               // prefix chunks per batch
#define CHLEN (NSEQ/NCH)        // 8
#define SN    2048              // sub-sort size

typedef unsigned long long ull;

#define FMA2(d, a, b) \
    asm("fma.rn.f32x2 %0, %1, %2, %0;" : "+l"(d) : "l"(a), "l"(b))
#define PACK2(out, f) \
    asm("mov.b64 %0, {%1, %1};" : "=l"(out) : "r"(__float_as_uint(f)))
#define UNPACK2(lo, hi, v) \
    do { unsigned int _l, _h; \
         asm("mov.b64 {%0, %1}, %2;" : "=r"(_l), "=r"(_h) : "l"(v)); \
         lo = __uint_as_float(_l); hi = __uint_as_float(_h); } while (0)

// ---------------- scratch ------------------------------------------------------------
__device__ __align__(16) float g_h[MTOT*KH];          // 4 MB projected feats
__device__ __align__(16) float g_wb[DIM];
__device__ __align__(16) float g_wc[DIM];
__device__ float g_t1[MTOT];
__device__ float g_t2[MTOT];
__device__ __align__(16) ull g_skey[BATCH][NSEQ];     // per-half sorted keys
__device__ float g_t2s[BATCH][NSEQ];                  // t2 sorted descending
__device__ int   g_perm[BATCH][NSEQ];
// chunk totals [b][k][c] (coalesced for scan loads)
__device__ __align__(16) float g_tot1[BATCH][KH][NCH];
__device__ __align__(16) float g_tot2[BATCH][KH][NCH];
__device__ __align__(16) float g_totz1[BATCH][NCH];
__device__ __align__(16) float g_totz2[BATCH][NCH];
// transposed exclusive offsets [b][c][k] (+ totals at c=NCH), coalesced for k_out
__device__ __align__(16) float g_off1T[BATCH][NCH+1][KH];
__device__ __align__(16) float g_off2T[BATCH][NCH+1][KH];
__device__ float g_offz1[BATCH][NCH+1];
__device__ float g_offz2[BATCH][NCH+1];

// ---------------- K0a: fold weights ---------------------------------------------------
__global__ void k_fold(const float* __restrict__ Wa, const float* __restrict__ Wb,
                       const float* __restrict__ Wc) {
    int d = threadIdx.x;                  // 512 threads
    float sb = 0.f, sc = 0.f;
#pragma unroll 8
    for (int k = 0; k < KH; k++) {
        float w = Wa[(size_t)k*DIM + d];
        sb += w * Wb[k];
        sc += w * Wc[k];
    }
    g_wb[d] = sb;
    g_wc[d] = sc;
}

// ---------------- K0b: t1/t2 directly from x (one warp per row) ----------------------
__global__ void k_t12(const float* __restrict__ x,
                      const float* __restrict__ wb_bias,
                      const float* __restrict__ wc_bias) {
    int lane = threadIdx.x & 31;
    int warp = threadIdx.x >> 5;          // 4 warps/block
    int row  = blockIdx.x*4 + warp;
    const float4* xr  = reinterpret_cast<const float4*>(x + (size_t)row*DIM);
    const float4* wb4 = reinterpret_cast<const float4*>(g_wb);
    const float4* wc4 = reinterpret_cast<const float4*>(g_wc);
    float s1 = 0.f, s2 = 0.f;
#pragma unroll
    for (int i = 0; i < 4; i++) {
        float4 xv = xr[lane + 32*i];
        float4 bv = wb4[lane + 32*i];
        float4 cv = wc4[lane + 32*i];
        s1 += xv.x*bv.x + xv.y*bv.y + xv.z*bv.z + xv.w*bv.w;
        s2 += xv.x*cv.x + xv.y*cv.y + xv.z*cv.z + xv.w*cv.w;
    }
#pragma unroll
    for (int s = 16; s; s >>= 1) {
        s1 += __shfl_xor_sync(0xFFFFFFFFu, s1, s);
        s2 += __shfl_xor_sync(0xFFFFFFFFu, s2, s);
    }
    if (lane == 0) {
        g_t1[row] = s1 + wb_bias[0];
        g_t2[row] = s2 + wc_bias[0];
    }
}

// ---------------- K1: h = x @ Wa^T, f32x2, register double-buffered (R10 proven) -----
__global__ void __launch_bounds__(256, 1)
k_gemm(const float* __restrict__ x, const float* __restrict__ Wa) {
    __shared__ __align__(16) float Xs[16*132];   // [dd][m], padded 132
    __shared__ __align__(16) float Ws[16*64];    // [dd][k]
    const int t  = threadIdx.x;          // 0..255
    const int m0 = blockIdx.x * 128;
    const int tm = t >> 4;               // rows tm*8..tm*8+7 (4 pairs)
    const int tk = t & 15;               // cols tk*4..tk*4+3

    const int xdg0 = t & 3,        xm0i = t >> 2;
    const int xdg1 = (t+256) & 3,  xm1i = (t+256) >> 2;
    const int wdg  = t & 3,        wk   = t >> 2;
    const float* xp0 = x  + (size_t)(m0 + xm0i)*DIM + xdg0*4;
    const float* xp1 = x  + (size_t)(m0 + xm1i)*DIM + xdg1*4;
    const float* wp  = Wa + (size_t)wk*DIM + wdg*4;

    ull acc2[4][4];
#pragma unroll
    for (int j = 0; j < 4; j++)
#pragma unroll
        for (int c = 0; c < 4; c++) acc2[j][c] = 0ull;

    float4 rx0 = *reinterpret_cast<const float4*>(xp0);
    float4 rx1 = *reinterpret_cast<const float4*>(xp1);
    float4 rw  = *reinterpret_cast<const float4*>(wp);

    for (int d0 = 0; d0 < DIM; d0 += 16) {
        Xs[(xdg0*4+0)*132 + xm0i] = rx0.x;
        Xs[(xdg0*4+1)*132 + xm0i] = rx0.y;
        Xs[(xdg0*4+2)*132 + xm0i] = rx0.z;
        Xs[(xdg0*4+3)*132 + xm0i] = rx0.w;
        Xs[(xdg1*4+0)*132 + xm1i] = rx1.x;
        Xs[(xdg1*4+1)*132 + xm1i] = rx1.y;
        Xs[(xdg1*4+2)*132 + xm1i] = rx1.z;
        Xs[(xdg1*4+3)*132 + xm1i] = rx1.w;
        Ws[(wdg*4+0)*64 + wk] = rw.x;
        Ws[(wdg*4+1)*64 + wk] = rw.y;
        Ws[(wdg*4+2)*64 + wk] = rw.z;
        Ws[(wdg*4+3)*64 + wk] = rw.w;
        __syncthreads();

        if (d0 + 16 < DIM) {
            rx0 = *reinterpret_cast<const float4*>(xp0 + d0 + 16);
            rx1 = *reinterpret_cast<const float4*>(xp1 + d0 + 16);
            rw  = *reinterpret_cast<const float4*>(wp  + d0 + 16);
        }

#pragma unroll
        for (int dd = 0; dd < 16; dd++) {
            ulonglong2 xa = *reinterpret_cast<const ulonglong2*>(Xs + dd*132 + tm*8);
            ulonglong2 xb = *reinterpret_cast<const ulonglong2*>(Xs + dd*132 + tm*8 + 4);
            float4 wv = *reinterpret_cast<const float4*>(Ws + dd*64 + tk*4);
            ull wd[4];
            PACK2(wd[0], wv.x);
            PACK2(wd[1], wv.y);
            PACK2(wd[2], wv.z);
            PACK2(wd[3], wv.w);
            ull xpq[4] = {xa.x, xa.y, xb.x, xb.y};
#pragma unroll
            for (int j = 0; j < 4; j++) {
                FMA2(acc2[j][0], xpq[j], wd[0]);
                FMA2(acc2[j][1], xpq[j], wd[1]);
                FMA2(acc2[j][2], xpq[j], wd[2]);
                FMA2(acc2[j][3], xpq[j], wd[3]);
            }
        }
        __syncthreads();
    }

    float acclo[4][4], acchi[4][4];
#pragma unroll
    for (int j = 0; j < 4; j++)
#pragma unroll
        for (int c = 0; c < 4; c++)
            UNPACK2(acclo[j][c], acchi[j][c], acc2[j][c]);

#pragma unroll
    for (int j = 0; j < 4; j++) {
        int mlo = m0 + tm*8 + 2*j;
        *reinterpret_cast<float4*>(g_h + (size_t)mlo*KH + tk*4) =
            make_float4(acclo[j][0],acclo[j][1],acclo[j][2],acclo[j][3]);
        *reinterpret_cast<float4*>(g_h + (size_t)(mlo+1)*KH + tk*4) =
            make_float4(acchi[j][0],acchi[j][1],acchi[j][2],acchi[j][3]);
    }
}

// ---------------- K2a: bitonic sort of 2048-element halves ----------------------------
__device__ __forceinline__ unsigned int fmap(float f) {
    unsigned int u = __float_as_uint(f);
    return (u & 0x80000000u) ? ~u : (u | 0x80000000u);
}
__device__ __forceinline__ float funmap(unsigned int u) {
    u = (u & 0x80000000u) ? (u & 0x7FFFFFFFu) : ~u;
    return __uint_as_float(u);
}

__global__ void k_sort2048() {
    __shared__ ull sv[SN];                   // 16 KB
    int b = blockIdx.x >> 1, half = blockIdx.x & 1;
    int tid = threadIdx.x;                   // 1024 threads
    for (int r = tid; r < SN; r += 1024) {
        int gi = half*SN + r;
        unsigned int u = fmap(g_t2[b*NSEQ + gi]);
        sv[r] = ((ull)u << 32) | (unsigned int)gi;
    }
    __syncthreads();
    int lane = tid & 31, warp = tid >> 5;
    for (int k = 2; k <= SN; k <<= 1) {
        for (int s = k >> 1; s >= 32; s >>= 1) {
#pragma unroll 1
            for (int t = tid; t < SN/2; t += 1024) {
                int i = ((t & ~(s-1)) << 1) | (t & (s-1));
                int j = i + s;
                bool desc = ((i & k) == 0);
                ull a = sv[i], c = sv[j];
                bool sw = desc ? (a < c) : (a > c);
                if (sw) { sv[i] = c; sv[j] = a; }
            }
            __syncthreads();
        }
        {
            int smax = ((k >> 1) < 32) ? (k >> 1) : 16;
#pragma unroll 1
            for (int g = warp; g < SN/32; g += 32) {
                int i = g*32 + lane;
                ull val = sv[i];
                bool desc = ((i & k) == 0);
#pragma unroll 1
                for (int s = smax; s >= 1; s >>= 1) {
                    ull other = __shfl_xor_sync(0xFFFFFFFFu, val, s);
                    bool upper = (lane & s) != 0;
                    bool takeMax = (upper != desc);
                    bool otherBigger = (other > val);
                    val = (takeMax == otherBigger) ? other : val;
                }
                sv[i] = val;
            }
            __syncthreads();
        }
    }
    for (int r = tid; r < SN; r += 1024)
        g_skey[b][half*SN + r] = sv[r];
}

// ---------------- K2b: merge (8 blocks; each ranks one half) --------------------------
__global__ void k_merge() {
    __shared__ ull sk[2*SN];                 // 32 KB
    int b = blockIdx.x >> 1, half = blockIdx.x & 1;
    int tid = threadIdx.x;                   // 1024 threads
    for (int r = tid; r < 2*SN; r += 1024)
        sk[r] = g_skey[b][r];
    __syncthreads();
#pragma unroll
    for (int q = 0; q < 2; q++) {
        int e = half*SN + tid + q*1024;
        ull key = sk[e];
        int ownIdx = e - half*SN;
        const ull* other = half ? sk : (sk + SN);
        int lo = 0, hi = SN;                 // count of other[] strictly greater
        while (lo < hi) {
            int mid = (lo + hi) >> 1;
            if (other[mid] > key) lo = mid + 1; else hi = mid;
        }
        int rank = ownIdx + lo;
        g_t2s[b][rank]  = funmap((unsigned int)(key >> 32));
        g_perm[b][rank] = (int)(key & 0xFFFFFFFFu);
    }
}

// ---------------- K3a: per-chunk totals ------------------------------------------------
__global__ void k_psum_a() {
    int b = blockIdx.x >> 9;              // NCH=512
    int c = blockIdx.x & 511;
    int k = threadIdx.x;                  // 64 threads
    int r0 = c * CHLEN;
    float m2 = g_t2s[b][0];
    float s1=0.f, s2=0.f, z1=0.f, z2=0.f;
#pragma unroll
    for (int r = r0; r < r0 + CHLEN; r++) {
        float tv = g_t2s[b][r] - m2;
        float e1 = expf(tv);
        float e2 = expf(0.2f*tv);
        int   j  = g_perm[b][r];
        float hv = g_h[((size_t)b*NSEQ + j)*KH + k];
        s1 += e1*hv;  s2 += e2*hv;
        z1 += e1;     z2 += e2;
    }
    g_tot1[b][k][c] = s1;  g_tot2[b][k][c] = s2;
    if (k == 0) { g_totz1[b][c] = z1; g_totz2[b][c] = z2; }
}

// ---------------- K3b: scan -> transposed offsets + totals ----------------------------
__global__ void k_scan() {
    int b = blockIdx.x >> 6, k = blockIdx.x & 63;
    int warp = threadIdx.x >> 5, lane = threadIdx.x & 31;
    if (warp == 0) {
        const float4* p1 = reinterpret_cast<const float4*>(&g_tot1[b][k][lane*16]);
        const float4* p2 = reinterpret_cast<const float4*>(&g_tot2[b][k][lane*16]);
        float v1[16], v2[16];
#pragma unroll
        for (int g = 0; g < 4; g++) {
            float4 a = p1[g], d = p2[g];
            v1[g*4+0]=a.x; v1[g*4+1]=a.y; v1[g*4+2]=a.z; v1[g*4+3]=a.w;
            v2[g*4+0]=d.x; v2[g*4+1]=d.y; v2[g*4+2]=d.z; v2[g*4+3]=d.w;
        }
        float t1 = 0.f, t2 = 0.f;
#pragma unroll
        for (int i = 0; i < 16; i++) {
            float a = v1[i], d = v2[i];
            v1[i] = t1; t1 += a;
            v2[i] = t2; t2 += d;
        }
        float e1 = t1, e2 = t2;
#pragma unroll
        for (int s = 1; s < 32; s <<= 1) {
            float o1 = __shfl_up_sync(0xFFFFFFFFu, e1, s);
            float o2 = __shfl_up_sync(0xFFFFFFFFu, e2, s);
            if (lane >= s) { e1 += o1; e2 += o2; }
        }
        e1 -= t1; e2 -= t2;                  // exclusive lane base
#pragma unroll
        for (int i = 0; i < 16; i++) {
            int c = lane*16 + i;
            g_off1T[b][c][k] = e1 + v1[i];
            g_off2T[b][c][k] = e2 + v2[i];
        }
        if (lane == 31) {                    // inclusive totals at c = NCH
            g_off1T[b][NCH][k] = e1 + t1;
            g_off2T[b][NCH][k] = e2 + t2;
        }
    } else if (k == 0) {
        float v1[16], v2[16];
        float t1 = 0.f, t2 = 0.f;
#pragma unroll
        for (int i = 0; i < 16; i++) {
            int c = lane*16 + i;
            float a = g_totz1[b][c];
            float d = g_totz2[b][c];
            v1[i] = t1; t1 += a;
            v2[i] = t2; t2 += d;
        }
        float e1 = t1, e2 = t2;
#pragma unroll
        for (int s = 1; s < 32; s <<= 1) {
            float o1 = __shfl_up_sync(0xFFFFFFFFu, e1, s);
            float o2 = __shfl_up_sync(0xFFFFFFFFu, e2, s);
            if (lane >= s) { e1 += o1; e2 += o2; }
        }
        e1 -= t1; e2 -= t2;
#pragma unroll
        for (int i = 0; i < 16; i++) {
            int c = lane*16 + i;
            g_offz1[b][c] = e1 + v1[i];
            g_offz2[b][c] = e2 + v2[i];
        }
        if (lane == 31) {
            g_offz1[b][NCH] = e1 + t1;
            g_offz2[b][NCH] = e2 + t2;
        }
    }
}

// ---------------- K4: output: search + on-the-fly chunk-local prefix ------------------
__global__ void k_out(float* __restrict__ out, const float* __restrict__ bias) {
    int lane = threadIdx.x & 31;
    int warp = threadIdx.x >> 5;          // 8 warps -> 8 rows per block
    int row  = blockIdx.x*8 + warp;
    int b    = row >> 12;

    float t1v = g_t1[row];
    float m2  = g_t2s[b][0];
    float u   = t1v + m2;
    float M   = (u > 0.f) ? u : 0.2f*u;
    float c1  = expf(u - M);
    float c2  = expf(0.2f*u - M);
    float tau = -t1v;

    const float* t2s = g_t2s[b];
    unsigned int b0 = __ballot_sync(0xFFFFFFFFu, t2s[lane*128]      > tau);
    unsigned int b1 = __ballot_sync(0xFFFFFFFFu, t2s[lane*128 + 64] > tau);
    int count1 = __popc(b0) + __popc(b1);
    int base   = count1 ? (count1 - 1) * 64 : 0;
    unsigned int d0 = __ballot_sync(0xFFFFFFFFu, t2s[base + lane]      > tau);
    unsigned int d1 = __ballot_sync(0xFFFFFFFFu, t2s[base + 32 + lane] > tau);
    int p = base + __popc(d0) + __popc(d1);

    int cp = p >> 3;                       // chunk index (cp=NCH iff p=NSEQ)
    int r0 = cp * CHLEN;
    int cnt = p - r0;

    int k0 = lane, k1 = lane + 32;
    float a1_0 = g_off1T[b][cp][k0], a1_1 = g_off1T[b][cp][k1];
    float a2_0 = g_off2T[b][cp][k0], a2_1 = g_off2T[b][cp][k1];
    float z1 = g_offz1[b][cp], z2 = g_offz2[b][cp];

#pragma unroll 1
    for (int r = r0; r < r0 + cnt; r++) {
        float tv = t2s[r] - m2;
        float e1 = expf(tv);
        float e2 = expf(0.2f*tv);
        int   j  = g_perm[b][r];
        const float* hr = g_h + ((size_t)b*NSEQ + j)*KH;
        float h0 = hr[k0], h1 = hr[k1];
        a1_0 += e1*h0;  a1_1 += e1*h1;
        a2_0 += e2*h0;  a2_1 += e2*h1;
        z1 += e1;  z2 += e2;
    }

    float Btot0 = g_off2T[b][NCH][k0];
    float Btot1 = g_off2T[b][NCH][k1];
    float Z2tot = g_offz2[b][NCH];
    float inv_den = 1.0f / (c1*z1 + c2*(Z2tot - z2));

    out[(size_t)row*KH + k0] = (c1*a1_0 + c2*(Btot0 - a2_0))*inv_den + bias[k0];
    out[(size_t)row*KH + k1] = (c1*a1_1 + c2*(Btot1 - a2_1))*inv_den + bias[k1];
}

// ---------------- stream/event objects ------------------------------------------------
struct ForkCtx {
    cudaStream_t s2;
    cudaEvent_t  evA, evB;
    ForkCtx() {
        cudaStreamCreateWithFlags(&s2, cudaStreamNonBlocking);
        cudaEventCreateWithFlags(&evA, cudaEventDisableTiming);
        cudaEventCreateWithFlags(&evB, cudaEventDisableTiming);
    }
};
static ForkCtx g_fork;

// ---------------- launch ---------------------------------------------------------------
extern "C" void kernel_launch(void* const* d_in, const int* in_sizes, int n_in,
                              void* d_out, int out_size) {
    const float* x       = (const float*)d_in[0];
    const float* Wa      = (const float*)d_in[1];
    const float* Wb      = (const float*)d_in[2];
    const float* wb_bias = (const float*)d_in[3];
    const float* Wc      = (const float*)d_in[4];
    const float* wc_bias = (const float*)d_in[5];
    const float* bias    = (const float*)d_in[6];
    float* out = (float*)d_out;

    k_fold<<<1, 512>>>(Wa, Wb, Wc);
    k_t12 <<<MTOT/4, 128>>>(x, wb_bias, wc_bias);
    cudaEventRecord(g_fork.evA, 0);
    cudaStreamWaitEvent(g_fork.s2, g_fork.evA, 0);
    k_sort2048<<<BATCH*2, 1024, 0, g_fork.s2>>>();
    k_merge   <<<BATCH*2, 1024, 0, g_fork.s2>>>();
    cudaEventRecord(g_fork.evB, g_fork.s2);

    k_gemm<<<MTOT/128, 256>>>(x, Wa);        // concurrent with sort path

    cudaStreamWaitEvent(0, g_fork.evB, 0);   // join
    k_psum_a<<<BATCH*NCH,  64>>>();
    k_scan  <<<BATCH*KH,   64>>>();
    k_out   <<<MTOT/8,   256>>>(out, bias);
}